// round 1
// baseline (speedup 1.0000x reference)
#include <cuda_runtime.h>

#define N_MAX 50000
#define F_IN 128
#define F_H  64

// Persistent scratch (no allocations allowed). All accumulator state is
// re-initialized every launch (graph replays must be deterministic).
__device__ float g_deg [N_MAX];
__device__ float g_dinv[N_MAX];
__device__ float g_h   [N_MAX * F_H];   // conv1 pre-aggregation features
__device__ float g_agg [N_MAX * F_H];   // conv1 aggregated output (pre-bias/tanh)
__device__ float g_h2  [N_MAX * F_H];   // conv2 pre-aggregation features
__device__ float g_agg2[N_MAX * F_H];   // conv2 aggregated output

// ---------------------------------------------------------------------------
// Degree / normalization
// ---------------------------------------------------------------------------
__global__ void k_init_deg(int n) {
    int i = blockIdx.x * blockDim.x + threadIdx.x;
    if (i < n) g_deg[i] = 1.0f;  // self-loop contributes 1
}

__global__ void k_count(const int* __restrict__ dst, int E) {
    int e = blockIdx.x * blockDim.x + threadIdx.x;
    if (e < E) atomicAdd(&g_deg[dst[e]], 1.0f);
}

__global__ void k_dinv(int n) {
    int i = blockIdx.x * blockDim.x + threadIdx.x;
    if (i < n) g_dinv[i] = rsqrtf(g_deg[i]);  // deg >= 1 always (self-loop)
}

// ---------------------------------------------------------------------------
// GEMM 1: h = x @ W1  (128 -> 64), also writes self-loop term into agg.
// Thread per node, W1 staged in shared.
// ---------------------------------------------------------------------------
__global__ void k_gemm1(const float* __restrict__ x,
                        const float* __restrict__ W, int n) {
    __shared__ float Ws[F_IN * F_H];  // 32 KB
    for (int i = threadIdx.x; i < F_IN * F_H; i += blockDim.x) Ws[i] = W[i];
    __syncthreads();

    int node = blockIdx.x * blockDim.x + threadIdx.x;
    if (node >= n) return;

    float acc[F_H];
#pragma unroll
    for (int j = 0; j < F_H; j++) acc[j] = 0.0f;

    const float4* xr = (const float4*)(x + (size_t)node * F_IN);
#pragma unroll 4
    for (int k4 = 0; k4 < F_IN / 4; k4++) {
        float4 xv = xr[k4];
        float xs[4] = {xv.x, xv.y, xv.z, xv.w};
#pragma unroll
        for (int kk = 0; kk < 4; kk++) {
            const float4* wr = (const float4*)(Ws + (k4 * 4 + kk) * F_H);
#pragma unroll
            for (int j4 = 0; j4 < F_H / 4; j4++) {
                float4 w = wr[j4];
                acc[j4 * 4 + 0] = fmaf(xs[kk], w.x, acc[j4 * 4 + 0]);
                acc[j4 * 4 + 1] = fmaf(xs[kk], w.y, acc[j4 * 4 + 1]);
                acc[j4 * 4 + 2] = fmaf(xs[kk], w.z, acc[j4 * 4 + 2]);
                acc[j4 * 4 + 3] = fmaf(xs[kk], w.w, acc[j4 * 4 + 3]);
            }
        }
    }

    float di = g_dinv[node];
    float sl = di * di;  // self-loop norm: dinv[n]*dinv[n]
    float4* hrow = (float4*)(g_h   + (size_t)node * F_H);
    float4* arow = (float4*)(g_agg + (size_t)node * F_H);
#pragma unroll
    for (int j4 = 0; j4 < F_H / 4; j4++) {
        float4 v = make_float4(acc[j4 * 4 + 0], acc[j4 * 4 + 1],
                               acc[j4 * 4 + 2], acc[j4 * 4 + 3]);
        hrow[j4] = v;
        arow[j4] = make_float4(v.x * sl, v.y * sl, v.z * sl, v.w * sl);
    }
}

// ---------------------------------------------------------------------------
// Edge scatter: agg[dst] += h[src] * dinv[src]*dinv[dst], vectorized red.v4.
// 16 threads per edge (one float4 each).
// ---------------------------------------------------------------------------
template <int LAYER>
__global__ void k_scatter(const int* __restrict__ src,
                          const int* __restrict__ dst, int E) {
    int idx = blockIdx.x * blockDim.x + threadIdx.x;
    if (idx >= E * 16) return;
    int e = idx >> 4;
    int c = idx & 15;

    int s = __ldg(src + e);
    int d = __ldg(dst + e);
    float nrm = g_dinv[s] * g_dinv[d];

    const float* h   = (LAYER == 0) ? g_h   : g_h2;
    float*       agg = (LAYER == 0) ? g_agg : g_agg2;

    float4 hv = *(const float4*)(h + (size_t)s * F_H + c * 4);
    float* p = agg + (size_t)d * F_H + c * 4;
    asm volatile("red.global.add.v4.f32 [%0], {%1, %2, %3, %4};"
                 :: "l"(p), "f"(hv.x * nrm), "f"(hv.y * nrm),
                    "f"(hv.z * nrm), "f"(hv.w * nrm)
                 : "memory");
}

// ---------------------------------------------------------------------------
// GEMM 2: z1 = tanh(agg1 + b1) applied on the fly; h2 = z1 @ W2 (64 -> 64);
// also writes self-loop term into agg2.
// ---------------------------------------------------------------------------
__global__ void k_gemm2(const float* __restrict__ b1,
                        const float* __restrict__ W, int n) {
    __shared__ float Ws[F_H * F_H];  // 16 KB
    __shared__ float bs[F_H];
    for (int i = threadIdx.x; i < F_H * F_H; i += blockDim.x) Ws[i] = W[i];
    if (threadIdx.x < F_H) bs[threadIdx.x] = b1[threadIdx.x];
    __syncthreads();

    int node = blockIdx.x * blockDim.x + threadIdx.x;
    if (node >= n) return;

    const float* a = g_agg + (size_t)node * F_H;
    float acc[F_H];
#pragma unroll
    for (int j = 0; j < F_H; j++) acc[j] = 0.0f;

#pragma unroll 4
    for (int k = 0; k < F_H; k++) {
        float rv = tanhf(__ldg(a + k) + bs[k]);
        const float4* wr = (const float4*)(Ws + k * F_H);
#pragma unroll
        for (int j4 = 0; j4 < F_H / 4; j4++) {
            float4 w = wr[j4];
            acc[j4 * 4 + 0] = fmaf(rv, w.x, acc[j4 * 4 + 0]);
            acc[j4 * 4 + 1] = fmaf(rv, w.y, acc[j4 * 4 + 1]);
            acc[j4 * 4 + 2] = fmaf(rv, w.z, acc[j4 * 4 + 2]);
            acc[j4 * 4 + 3] = fmaf(rv, w.w, acc[j4 * 4 + 3]);
        }
    }

    float di = g_dinv[node];
    float sl = di * di;
    float4* hrow = (float4*)(g_h2   + (size_t)node * F_H);
    float4* arow = (float4*)(g_agg2 + (size_t)node * F_H);
#pragma unroll
    for (int j4 = 0; j4 < F_H / 4; j4++) {
        float4 v = make_float4(acc[j4 * 4 + 0], acc[j4 * 4 + 1],
                               acc[j4 * 4 + 2], acc[j4 * 4 + 3]);
        hrow[j4] = v;
        arow[j4] = make_float4(v.x * sl, v.y * sl, v.z * sl, v.w * sl);
    }
}

// ---------------------------------------------------------------------------
// Fused FC head: z2 = tanh(agg2 + b2); t = tanh(z2 @ fcW1 + fb1);
// out = t @ fcW2 + fb2.  Thread per node.
// ---------------------------------------------------------------------------
__global__ void k_fc(const float* __restrict__ b2,
                     const float* __restrict__ fw1, const float* __restrict__ fb1,
                     const float* __restrict__ fw2, const float* __restrict__ fb2,
                     float* __restrict__ out, int n) {
    __shared__ float W1s[F_H * 32];  // 8 KB
    __shared__ float b2s[F_H];
    __shared__ float W2s[32];
    __shared__ float b1s[32];
    for (int i = threadIdx.x; i < F_H * 32; i += blockDim.x) W1s[i] = fw1[i];
    if (threadIdx.x < F_H) b2s[threadIdx.x] = b2[threadIdx.x];
    if (threadIdx.x < 32) {
        W2s[threadIdx.x] = fw2[threadIdx.x];
        b1s[threadIdx.x] = fb1[threadIdx.x];
    }
    __syncthreads();

    int node = blockIdx.x * blockDim.x + threadIdx.x;
    if (node >= n) return;

    const float* a = g_agg2 + (size_t)node * F_H;
    float acc[32];
#pragma unroll
    for (int j = 0; j < 32; j++) acc[j] = 0.0f;

#pragma unroll 4
    for (int k = 0; k < F_H; k++) {
        float rv = tanhf(__ldg(a + k) + b2s[k]);
        const float4* wr = (const float4*)(W1s + k * 32);
#pragma unroll
        for (int j4 = 0; j4 < 8; j4++) {
            float4 w = wr[j4];
            acc[j4 * 4 + 0] = fmaf(rv, w.x, acc[j4 * 4 + 0]);
            acc[j4 * 4 + 1] = fmaf(rv, w.y, acc[j4 * 4 + 1]);
            acc[j4 * 4 + 2] = fmaf(rv, w.z, acc[j4 * 4 + 2]);
            acc[j4 * 4 + 3] = fmaf(rv, w.w, acc[j4 * 4 + 3]);
        }
    }

    float r = fb2[0];
#pragma unroll
    for (int j = 0; j < 32; j++) r = fmaf(tanhf(acc[j] + b1s[j]), W2s[j], r);
    out[node] = r;
}

// ---------------------------------------------------------------------------
extern "C" void kernel_launch(void* const* d_in, const int* in_sizes, int n_in,
                              void* d_out, int out_size) {
    const float* x   = (const float*)d_in[0];
    const int*   ei  = (const int*)  d_in[1];
    const float* w1  = (const float*)d_in[2];
    const float* b1  = (const float*)d_in[3];
    const float* w2  = (const float*)d_in[4];
    const float* b2  = (const float*)d_in[5];
    const float* fw1 = (const float*)d_in[6];
    const float* fb1 = (const float*)d_in[7];
    const float* fw2 = (const float*)d_in[8];
    const float* fb2 = (const float*)d_in[9];

    int n = in_sizes[0] / F_IN;      // 50000
    int E = in_sizes[1] / 2;         // 800000
    const int* src = ei;
    const int* dst = ei + E;
    float* out = (float*)d_out;

    k_init_deg<<<(n + 255) / 256, 256>>>(n);
    k_count  <<<(E + 255) / 256, 256>>>(dst, E);
    k_dinv   <<<(n + 255) / 256, 256>>>(n);

    k_gemm1<<<(n + 127) / 128, 128>>>(x, w1, n);
    k_scatter<0><<<(E * 16 + 255) / 256, 256>>>(src, dst, E);

    k_gemm2<<<(n + 127) / 128, 128>>>(b1, w2, n);
    k_scatter<1><<<(E * 16 + 255) / 256, 256>>>(src, dst, E);

    k_fc<<<(n + 127) / 128, 128>>>(b2, fw1, fb1, fw2, fb2, out, n);
}